// round 2
// baseline (speedup 1.0000x reference)
#include <cuda_runtime.h>
#include <cstdint>

// ---------------------------------------------------------------------------
// TT-linear, exploiting the rank-64 bottleneck:
//   W = A(4096x64) @ B(64x4096);  y = (x @ B^T) @ A^T + b
// Scratch (no allocations allowed -> __device__ globals)
// ---------------------------------------------------------------------------
__device__ __align__(256) float g_w01[16 * 1024];      // fold(core0,core1): (16,1024)
__device__ __align__(256) float g_A[256 * 1024];       // A flat: (4096,64) == (256,1024)
__device__ __align__(256) float g_B1[1024 * 1024];     // fold(core3,core4): (1024,1024)
__device__ __align__(256) float g_B[64 * 4096];        // B: (64,4096)
__device__ __align__(256) float g_T[2][8192 * 64];     // split-K partials of t = x @ B^T

// Packed f32x2 FMA (Blackwell; ptxas won't auto-fuse, must come from PTX)
__device__ __forceinline__ float2 ffma2(float2 a, float2 b, float2 c) {
    unsigned long long ra = *reinterpret_cast<unsigned long long*>(&a);
    unsigned long long rb = *reinterpret_cast<unsigned long long*>(&b);
    unsigned long long rc = *reinterpret_cast<unsigned long long*>(&c);
    unsigned long long rd;
    asm("fma.rn.f32x2 %0, %1, %2, %3;" : "=l"(rd) : "l"(ra), "l"(rb), "l"(rc));
    return *reinterpret_cast<float2*>(&rd);
}

// ---------------------------------------------------------------------------
// Fold kernels (tiny): build A and B from the 6 TT cores.
// core shapes: G0(1,16,64) G1(64,16,64) G2(64,16,64) G3(64,16,64) G4(64,16,64) G5(64,16,1)
// ---------------------------------------------------------------------------
__global__ void fold1_kernel(const float* __restrict__ G0, const float* __restrict__ G1) {
    // w01[s0][(s1,r2)] = sum_r1 G0[s0,r1] * G1[r1,(s1,r2)]   (16 x 1024)
    int i = blockIdx.x * 256 + threadIdx.x;   // 16384
    int row = i >> 10, col = i & 1023;
    float s = 0.f;
#pragma unroll 16
    for (int r1 = 0; r1 < 64; ++r1) s += G0[row * 64 + r1] * G1[r1 * 1024 + col];
    g_w01[i] = s;
}

__global__ void fold2_kernel(const float* __restrict__ G2) {
    // A[(s0,s1),(s2,r3)] = sum_r2 w01[(s0,s1),r2] * G2[r2,(s2,r3)]   (256 x 1024)
    // flat (256,1024) row-major == flat (4096,64) row-major -> store at i directly
    int i = blockIdx.x * 256 + threadIdx.x;   // 262144
    int row = i >> 10, col = i & 1023;
    float s = 0.f;
#pragma unroll 16
    for (int r2 = 0; r2 < 64; ++r2) s += g_w01[row * 64 + r2] * G2[r2 * 1024 + col];
    g_A[i] = s;
}

__global__ void foldB1_kernel(const float* __restrict__ G3, const float* __restrict__ G4) {
    // B1[(r3,s3),(s4,r5)] = sum_r4 G3[(r3,s3),r4] * G4[r4,(s4,r5)]   (1024 x 1024)
    int i = blockIdx.x * 256 + threadIdx.x;   // 1048576
    int row = i >> 10, col = i & 1023;
    float s = 0.f;
#pragma unroll 16
    for (int r4 = 0; r4 < 64; ++r4) s += G3[row * 64 + r4] * G4[r4 * 1024 + col];
    g_B1[i] = s;
}

__global__ void foldB2_kernel(const float* __restrict__ G5) {
    // B[r3,(s3,s4,s5)] = sum_r5 B1[(r3,s3,s4),r5] * G5[r5,s5]
    // flat index of output == i (checked: r3*4096 + (s3*16+s4)*16 + s5 == row*16+s5)
    int i = blockIdx.x * 256 + threadIdx.x;   // 262144
    int row = i >> 4, s5 = i & 15;
    float s = 0.f;
#pragma unroll
    for (int r5 = 0; r5 < 64; ++r5) s += g_B1[row * 64 + r5] * G5[r5 * 16 + s5];
    g_B[i] = s;
}

// ---------------------------------------------------------------------------
// GEMM1: t[n,r] = sum_k x[n,k] * B[r,k]     M=8192, N=64, K=4096
// Split-K=2 (grid 128x2 -> 256 blocks for occupancy). Block: 64 tok x 64 r,
// 128 threads, thread tile 8 tok x 4 r (as 2 f32x2 pairs). All inner-loop
// smem reads are bank-conflict-free (r strided by 16 across the jj dim).
// ---------------------------------------------------------------------------
__global__ __launch_bounds__(128) void gemm1_kernel(const float* __restrict__ x) {
    __shared__ float sx[64][33];   // [tok][k]
    __shared__ float sb[64][33];   // [r][k]
    const int tid = threadIdx.x;
    const int tx = tid & 15;       // r = tx + 16*jj, jj in 0..3
    const int ty = tid >> 4;       // tokens ty*8 .. ty*8+7
    const int tok0 = blockIdx.x * 64;
    const int ky = blockIdx.y;     // K half
    const int kbase = ky * 2048;

    float2 acc[8][2];
#pragma unroll
    for (int i = 0; i < 8; ++i) { acc[i][0] = make_float2(0.f, 0.f); acc[i][1] = make_float2(0.f, 0.f); }

    for (int k0 = kbase; k0 < kbase + 2048; k0 += 32) {
        // fill tiles: 64x32 each, 128 threads x 4 float4
#pragma unroll
        for (int l = 0; l < 4; ++l) {
            int s = tid + 128 * l;        // 0..511 float4 slots
            int row = s >> 3;             // 0..63
            int kq = (s & 7) * 4;         // 0..28
            float4 v = *reinterpret_cast<const float4*>(&x[(size_t)(tok0 + row) * 4096 + k0 + kq]);
            sx[row][kq + 0] = v.x; sx[row][kq + 1] = v.y; sx[row][kq + 2] = v.z; sx[row][kq + 3] = v.w;
            float4 w = *reinterpret_cast<const float4*>(&g_B[(size_t)row * 4096 + k0 + kq]);
            sb[row][kq + 0] = w.x; sb[row][kq + 1] = w.y; sb[row][kq + 2] = w.z; sb[row][kq + 3] = w.w;
        }
        __syncthreads();

#pragma unroll
        for (int kk = 0; kk < 32; ++kk) {
            float a[8];
#pragma unroll
            for (int i = 0; i < 8; ++i) a[i] = sx[ty * 8 + i][kk];
            float2 bp0 = make_float2(sb[tx][kk],      sb[tx + 16][kk]);
            float2 bp1 = make_float2(sb[tx + 32][kk], sb[tx + 48][kk]);
#pragma unroll
            for (int i = 0; i < 8; ++i) {
                float2 av = make_float2(a[i], a[i]);
                acc[i][0] = ffma2(av, bp0, acc[i][0]);
                acc[i][1] = ffma2(av, bp1, acc[i][1]);
            }
        }
        __syncthreads();
    }

#pragma unroll
    for (int i = 0; i < 8; ++i) {
        int n = tok0 + ty * 8 + i;
        float* tr = &g_T[ky][(size_t)n * 64];
        tr[tx]      = acc[i][0].x;
        tr[tx + 16] = acc[i][0].y;
        tr[tx + 32] = acc[i][1].x;
        tr[tx + 48] = acc[i][1].y;
    }
}

// ---------------------------------------------------------------------------
// GEMM2: y[n,o] = sum_r t[n,r] * A[o,r] + b[o]   M=8192, N=4096, K=64
// Block: 64 tok x 128 out, 128 threads, thread tile 8 tok x 8 out.
// K=64 entirely in smem; t split-K partials reduced during tile load.
// out assigned strided (out = tx + 16*jj) -> conflict-free scalar b-reads.
// ---------------------------------------------------------------------------
__global__ __launch_bounds__(128) void gemm2_kernel(const float* __restrict__ bias,
                                                    float* __restrict__ y) {
    extern __shared__ float smem[];
    float (*st)[65] = reinterpret_cast<float (*)[65]>(smem);             // [64 tok][65]
    float (*sa)[65] = reinterpret_cast<float (*)[65]>(smem + 64 * 65);   // [128 out][65]
    const int tid = threadIdx.x;
    const int tx = tid & 15;     // out = tx + 16*jj, jj in 0..7
    const int ty = tid >> 4;     // tokens ty*8 .. ty*8+7
    const int tok0 = blockIdx.x * 64;
    const int out0 = blockIdx.y * 128;

    // t tile 64x64 (reduce the two split-K partials while loading)
#pragma unroll
    for (int l = 0; l < 8; ++l) {
        int s = tid + 128 * l;     // 0..1023 float4 slots
        int row = s >> 4;          // 0..63
        int c = (s & 15) * 4;
        float4 v0 = *reinterpret_cast<const float4*>(&g_T[0][(size_t)(tok0 + row) * 64 + c]);
        float4 v1 = *reinterpret_cast<const float4*>(&g_T[1][(size_t)(tok0 + row) * 64 + c]);
        st[row][c + 0] = v0.x + v1.x; st[row][c + 1] = v0.y + v1.y;
        st[row][c + 2] = v0.z + v1.z; st[row][c + 3] = v0.w + v1.w;
    }
    // A tile 128x64
#pragma unroll
    for (int l = 0; l < 16; ++l) {
        int s = tid + 128 * l;     // 0..2047 float4 slots
        int row = s >> 4;          // 0..127
        int c = (s & 15) * 4;
        float4 v = *reinterpret_cast<const float4*>(&g_A[(size_t)(out0 + row) * 64 + c]);
        sa[row][c + 0] = v.x; sa[row][c + 1] = v.y; sa[row][c + 2] = v.z; sa[row][c + 3] = v.w;
    }
    __syncthreads();

    float2 acc[8][4];
#pragma unroll
    for (int i = 0; i < 8; ++i)
#pragma unroll
        for (int p = 0; p < 4; ++p) acc[i][p] = make_float2(0.f, 0.f);

#pragma unroll
    for (int r = 0; r < 64; ++r) {
        float a[8];
#pragma unroll
        for (int i = 0; i < 8; ++i) a[i] = st[ty * 8 + i][r];
        float2 bp[4];
#pragma unroll
        for (int p = 0; p < 4; ++p)
            bp[p] = make_float2(sa[tx + 16 * (2 * p)][r], sa[tx + 16 * (2 * p + 1)][r]);
#pragma unroll
        for (int i = 0; i < 8; ++i) {
            float2 av = make_float2(a[i], a[i]);
#pragma unroll
            for (int p = 0; p < 4; ++p) acc[i][p] = ffma2(av, bp[p], acc[i][p]);
        }
    }

    float bv[8];
#pragma unroll
    for (int jj = 0; jj < 8; ++jj) bv[jj] = bias[out0 + tx + 16 * jj];

#pragma unroll
    for (int i = 0; i < 8; ++i) {
        int n = tok0 + ty * 8 + i;
        float* yr = y + (size_t)n * 4096 + out0;
#pragma unroll
        for (int p = 0; p < 4; ++p) {
            yr[tx + 16 * (2 * p)]     = acc[i][p].x + bv[2 * p];
            yr[tx + 16 * (2 * p + 1)] = acc[i][p].y + bv[2 * p + 1];
        }
    }
}

// ---------------------------------------------------------------------------
// Launch
// ---------------------------------------------------------------------------
extern "C" void kernel_launch(void* const* d_in, const int* in_sizes, int n_in,
                              void* d_out, int out_size) {
    // Robust input identification by element count (core0/core5 by order):
    //   core0: 1024, core1..4: 65536, core5: 1024, x: 33554432, b: 4096
    const float* core[6] = {nullptr, nullptr, nullptr, nullptr, nullptr, nullptr};
    const float* x = nullptr;
    const float* bias = nullptr;
    int c64 = 1;
    for (int i = 0; i < n_in; ++i) {
        int sz = in_sizes[i];
        const float* p = reinterpret_cast<const float*>(d_in[i]);
        if (sz == 8192 * 4096) x = p;
        else if (sz == 4096) bias = p;
        else if (sz == 65536) { if (c64 <= 4) core[c64++] = p; }
        else if (sz == 1024) { if (!core[0]) core[0] = p; else core[5] = p; }
    }
    float* y = reinterpret_cast<float*>(d_out);

    const int g2_smem = (64 * 65 + 128 * 65) * (int)sizeof(float);  // 49920 B
    cudaFuncSetAttribute(gemm2_kernel, cudaFuncAttributeMaxDynamicSharedMemorySize, g2_smem);

    fold1_kernel<<<64, 256>>>(core[0], core[1]);
    fold2_kernel<<<1024, 256>>>(core[2]);
    foldB1_kernel<<<4096, 256>>>(core[3], core[4]);
    foldB2_kernel<<<1024, 256>>>(core[5]);
    gemm1_kernel<<<dim3(128, 2), 128>>>(x);
    gemm2_kernel<<<dim3(128, 32), 128, g2_smem>>>(bias, y);
}

// round 5
// speedup vs baseline: 1.6688x; 1.6688x over previous
#include <cuda_runtime.h>
#include <cstdint>

// ===========================================================================
// TT-linear via rank-64 bottleneck:  W = A(4096x64) @ B(64x4096)
//   t = x @ B^T      (mma.sync tf32, cp.async 4-stage pipeline)
//   y = t @ A^T + b  (mma.sync tf32, K=64 one-shot)
// Weights & t are rna-rounded to tf32 at producer side; x is HW-truncated.
// ===========================================================================
__device__ __align__(256) float g_w01[16 * 1024];   // fold(core0,core1)
__device__ __align__(256) float g_A[4096 * 64];     // A (out, r)   tf32-rounded
__device__ __align__(256) float g_G45[64 * 256];    // fold(core4,core5)
__device__ __align__(256) float g_B[64 * 4096];     // B (r, in)    tf32-rounded
__device__ __align__(256) float g_t[8192 * 64];     // t = x@B^T    tf32-rounded

// ---------------- helpers ---------------------------------------------------
__device__ __forceinline__ uint32_t smem_u32(const void* p) {
    uint32_t a;
    asm("{ .reg .u64 t; cvta.to.shared.u64 t, %1; cvt.u32.u64 %0, t; }" : "=r"(a) : "l"(p));
    return a;
}
__device__ __forceinline__ float rna(float v) {
    uint32_t r; asm("cvt.rna.tf32.f32 %0, %1;" : "=r"(r) : "f"(v));
    return __uint_as_float(r);
}
__device__ __forceinline__ void cp16(uint32_t dst, const void* src) {
    asm volatile("cp.async.cg.shared.global [%0], [%1], 16;" :: "r"(dst), "l"(src));
}
#define CP_COMMIT() asm volatile("cp.async.commit_group;" ::: "memory")
#define CP_WAIT2()  asm volatile("cp.async.wait_group 2;" ::: "memory")

// D += A * B   (m16n8k8, tf32 inputs in b32 regs, f32 accum)
__device__ __forceinline__ void mma8(float* c, const uint32_t* a, const uint32_t* b) {
    asm volatile(
        "mma.sync.aligned.m16n8k8.row.col.f32.tf32.tf32.f32 "
        "{%0,%1,%2,%3}, {%4,%5,%6,%7}, {%8,%9}, {%0,%1,%2,%3};"
        : "+f"(c[0]), "+f"(c[1]), "+f"(c[2]), "+f"(c[3])
        : "r"(a[0]), "r"(a[1]), "r"(a[2]), "r"(a[3]), "r"(b[0]), "r"(b[1]));
}

// ---------------------------------------------------------------------------
// Folds. Core shapes: G0(1,16,64) G1..G4(64,16,64) G5(64,16,1).
// Flat-layout equivalences verified in R1 (rel_err 5e-7 on the fp32 path).
// ---------------------------------------------------------------------------
__global__ void fold1_kernel(const float* __restrict__ G0, const float* __restrict__ G1) {
    int i = blockIdx.x * 256 + threadIdx.x;       // 16384: w01[s0][(s1,r2)]
    int row = i >> 10, col = i & 1023;
    float s = 0.f;
#pragma unroll 16
    for (int r1 = 0; r1 < 64; ++r1) s += G0[row * 64 + r1] * G1[r1 * 1024 + col];
    g_w01[i] = s;
}

__global__ void fold2_kernel(const float* __restrict__ G2) {
    // A[(s0,s1)][(s2,r3)]; flat (256,1024) == (4096,64) row-major.
    int c = blockIdx.y * 256 + threadIdx.x;       // 1024 cols
    int r0 = blockIdx.x * 8;                      // 256 rows / 8
    float acc[8] = {0, 0, 0, 0, 0, 0, 0, 0};
    for (int r2 = 0; r2 < 64; ++r2) {
        float g = G2[r2 * 1024 + c];
#pragma unroll
        for (int j = 0; j < 8; ++j) acc[j] += g_w01[(r0 + j) * 64 + r2] * g;
    }
#pragma unroll
    for (int j = 0; j < 8; ++j) g_A[(size_t)(r0 + j) * 1024 + c] = rna(acc[j]);
}

__global__ void foldG45_kernel(const float* __restrict__ G4, const float* __restrict__ G5) {
    int i = blockIdx.x * 256 + threadIdx.x;       // 16384: G45[r4][(s4,s5)]
    int r4 = i >> 8, s4 = (i >> 4) & 15, s5 = i & 15;
    float s = 0.f;
#pragma unroll
    for (int r5 = 0; r5 < 64; ++r5) s += G4[r4 * 1024 + s4 * 64 + r5] * G5[r5 * 16 + s5];
    g_G45[i] = s;
}

__global__ void foldB_kernel(const float* __restrict__ G3) {
    // B[(r3,s3)][(s4,s5)]: flat (1024,256) == (64,4096) row-major.
    int c = threadIdx.x;                          // 256 cols
    int rs0 = blockIdx.x * 8;                     // 1024 rows / 8
    float acc[8] = {0, 0, 0, 0, 0, 0, 0, 0};
    for (int r4 = 0; r4 < 64; ++r4) {
        float g = g_G45[r4 * 256 + c];
#pragma unroll
        for (int j = 0; j < 8; ++j) acc[j] += G3[(rs0 + j) * 64 + r4] * g;
    }
#pragma unroll
    for (int j = 0; j < 8; ++j) g_B[(size_t)(rs0 + j) * 256 + c] = rna(acc[j]);
}

// ---------------------------------------------------------------------------
// GEMM1: t[n,r] = sum_k x[n,k] * B[r,k].   M=8192 N=64 K=4096.
// 128 CTAs of 64 tok x 64 r, 256 threads (8 warps, 2x4; warp tile 32x16).
// K chunks of 32, 4-stage cp.async ring. smem rows padded to 36 floats.
//   stage s: x tile at s*18432, B tile at s*18432+9216 (64 rows x 144 B each)
// ---------------------------------------------------------------------------
__global__ __launch_bounds__(256) void gemm1_kernel(const float* __restrict__ x) {
    extern __shared__ char sm[];
    const uint32_t sb = smem_u32(sm);
    const int tid = threadIdx.x;
    const int warp = tid >> 5, lane = tid & 31;
    const int wm = warp >> 2, wn = warp & 3;       // warp tile origin (wm*32, wn*16)
    const int tok0 = blockIdx.x * 64;
    const int qr = (tid & 7) * 4;                  // float col within 32-chunk
    const int row0 = tid >> 3;                     // 0..31  (two rows per thread: +32)

    float acc[2][2][4];
#pragma unroll
    for (int a = 0; a < 2; ++a)
#pragma unroll
        for (int b = 0; b < 2; ++b)
#pragma unroll
            for (int c = 0; c < 4; ++c) acc[a][b][c] = 0.f;

    // issue one chunk into stage s
    auto issue = [&](int chunk, int s) {
        int kc = chunk * 32;
        uint32_t xd = sb + s * 18432;
        uint32_t bd = xd + 9216;
#pragma unroll
        for (int l = 0; l < 2; ++l) {
            int r = row0 + 32 * l;
            cp16(xd + (uint32_t)(r * 144 + qr * 4), &x[(size_t)(tok0 + r) * 4096 + kc + qr]);
            cp16(bd + (uint32_t)(r * 144 + qr * 4), &g_B[(size_t)r * 4096 + kc + qr]);
        }
    };

    issue(0, 0); CP_COMMIT();
    issue(1, 1); CP_COMMIT();
    issue(2, 2); CP_COMMIT();

    const int lr = lane >> 2, lc = lane & 3;
    for (int i = 0; i < 128; ++i) {
        CP_WAIT2();
        __syncthreads();
        if (i + 3 < 128) issue(i + 3, (i + 3) & 3);
        CP_COMMIT();   // empty group near the tail keeps wait_group 2 uniform

        const float* xs = reinterpret_cast<const float*>(sm + (i & 3) * 18432);
        const float* bs = reinterpret_cast<const float*>(sm + (i & 3) * 18432 + 9216);
#pragma unroll
        for (int k8 = 0; k8 < 4; ++k8) {
            const int kk = k8 * 8 + lc;
            uint32_t af[2][4], bf[2][2];
#pragma unroll
            for (int mt = 0; mt < 2; ++mt) {
                int r = wm * 32 + mt * 16 + lr;
                af[mt][0] = __float_as_uint(xs[r * 36 + kk]);
                af[mt][1] = __float_as_uint(xs[(r + 8) * 36 + kk]);
                af[mt][2] = __float_as_uint(xs[r * 36 + kk + 4]);
                af[mt][3] = __float_as_uint(xs[(r + 8) * 36 + kk + 4]);
            }
#pragma unroll
            for (int nt = 0; nt < 2; ++nt) {
                int n = wn * 16 + nt * 8 + lr;
                bf[nt][0] = __float_as_uint(bs[n * 36 + kk]);
                bf[nt][1] = __float_as_uint(bs[n * 36 + kk + 4]);
            }
#pragma unroll
            for (int mt = 0; mt < 2; ++mt)
#pragma unroll
                for (int nt = 0; nt < 2; ++nt) mma8(acc[mt][nt], af[mt], bf[nt]);
        }
    }

    // epilogue: t (tf32-rounded), float2 stores; each quad covers 32 B.
#pragma unroll
    for (int mt = 0; mt < 2; ++mt)
#pragma unroll
        for (int nt = 0; nt < 2; ++nt)
#pragma unroll
            for (int h = 0; h < 2; ++h) {
                int r = tok0 + wm * 32 + mt * 16 + lr + 8 * h;
                int c = wn * 16 + nt * 8 + 2 * lc;
                float2 v = make_float2(rna(acc[mt][nt][2 * h]), rna(acc[mt][nt][2 * h + 1]));
                *reinterpret_cast<float2*>(&g_t[(size_t)r * 64 + c]) = v;
            }
}

// ---------------------------------------------------------------------------
// GEMM2: y[n,o] = sum_r t[n,r] * A[o,r] + b[o].   M=8192 N=4096 K=64.
// 2048 CTAs of 128 tok x 128 out, 256 threads (8 warps 2x4; warp tile 64x32).
// K=64 one-shot in smem (rows padded to 68 floats). Direct STG epilogue.
// ---------------------------------------------------------------------------
__global__ __launch_bounds__(256, 2) void gemm2_kernel(const float* __restrict__ bias,
                                                       float* __restrict__ y) {
    extern __shared__ char sm[];
    float* st = reinterpret_cast<float*>(sm);                 // [128][68]
    float* sa = reinterpret_cast<float*>(sm) + 128 * 68;      // [128][68]
    const int tid = threadIdx.x;
    const int warp = tid >> 5, lane = tid & 31;
    const int wm = warp >> 2, wn = warp & 3;       // warp tile origin (wm*64, wn*32)
    const int tok0 = blockIdx.x * 128, out0 = blockIdx.y * 128;

    // load tiles: 128x64 floats each = 2048 float4; 8 per thread
#pragma unroll
    for (int l = 0; l < 8; ++l) {
        int s = tid + 256 * l, row = s >> 4, q = (s & 15) * 4;
        float4 v = *reinterpret_cast<const float4*>(&g_t[(size_t)(tok0 + row) * 64 + q]);
        *reinterpret_cast<float4*>(&st[row * 68 + q]) = v;
        float4 w = *reinterpret_cast<const float4*>(&g_A[(size_t)(out0 + row) * 64 + q]);
        *reinterpret_cast<float4*>(&sa[row * 68 + q]) = w;
    }
    __syncthreads();

    float acc[4][4][4];
#pragma unroll
    for (int a = 0; a < 4; ++a)
#pragma unroll
        for (int b = 0; b < 4; ++b)
#pragma unroll
            for (int c = 0; c < 4; ++c) acc[a][b][c] = 0.f;

    const int lr = lane >> 2, lc = lane & 3;
#pragma unroll
    for (int k8 = 0; k8 < 8; ++k8) {
        const int kk = k8 * 8 + lc;
        uint32_t af[4][4], bf[4][2];
#pragma unroll
        for (int mt = 0; mt < 4; ++mt) {
            int r = wm * 64 + mt * 16 + lr;
            af[mt][0] = __float_as_uint(st[r * 68 + kk]);
            af[mt][1] = __float_as_uint(st[(r + 8) * 68 + kk]);
            af[mt][2] = __float_as_uint(st[r * 68 + kk + 4]);
            af[mt][3] = __float_as_uint(st[(r + 8) * 68 + kk + 4]);
        }
#pragma unroll
        for (int nt = 0; nt < 4; ++nt) {
            int n = wn * 32 + nt * 8 + lr;
            bf[nt][0] = __float_as_uint(sa[n * 68 + kk]);
            bf[nt][1] = __float_as_uint(sa[n * 68 + kk + 4]);
        }
#pragma unroll
        for (int mt = 0; mt < 4; ++mt)
#pragma unroll
            for (int nt = 0; nt < 4; ++nt) mma8(acc[mt][nt], af[mt], bf[nt]);
    }

    // bias per n-tile (cols 2*lc, 2*lc+1 within the 8-wide tile)
    float2 bv[4];
#pragma unroll
    for (int nt = 0; nt < 4; ++nt)
        bv[nt] = *reinterpret_cast<const float2*>(&bias[out0 + wn * 32 + nt * 8 + 2 * lc]);

#pragma unroll
    for (int mt = 0; mt < 4; ++mt)
#pragma unroll
        for (int h = 0; h < 2; ++h) {
            int r = tok0 + wm * 64 + mt * 16 + lr + 8 * h;
            float* yr = y + (size_t)r * 4096 + out0 + wn * 32;
#pragma unroll
            for (int nt = 0; nt < 4; ++nt) {
                float2 v = make_float2(acc[mt][nt][2 * h] + bv[nt].x,
                                       acc[mt][nt][2 * h + 1] + bv[nt].y);
                *reinterpret_cast<float2*>(&yr[nt * 8 + 2 * lc]) = v;
            }
        }
}

// ---------------------------------------------------------------------------
// Launch
// ---------------------------------------------------------------------------
extern "C" void kernel_launch(void* const* d_in, const int* in_sizes, int n_in,
                              void* d_out, int out_size) {
    const float* core[6] = {nullptr, nullptr, nullptr, nullptr, nullptr, nullptr};
    const float* x = nullptr;
    const float* bias = nullptr;
    int c64 = 1;
    for (int i = 0; i < n_in; ++i) {
        int sz = in_sizes[i];
        const float* p = reinterpret_cast<const float*>(d_in[i]);
        if (sz == 8192 * 4096) x = p;
        else if (sz == 4096) bias = p;
        else if (sz == 65536) { if (c64 <= 4) core[c64++] = p; }
        else if (sz == 1024) { if (!core[0]) core[0] = p; else core[5] = p; }
    }
    float* y = reinterpret_cast<float*>(d_out);

    const int g1_smem = 4 * 18432;                 // 73728
    const int g2_smem = 2 * 128 * 68 * 4;          // 69632
    cudaFuncSetAttribute(gemm1_kernel, cudaFuncAttributeMaxDynamicSharedMemorySize, g1_smem);
    cudaFuncSetAttribute(gemm2_kernel, cudaFuncAttributeMaxDynamicSharedMemorySize, g2_smem);

    fold1_kernel<<<64, 256>>>(core[0], core[1]);
    fold2_kernel<<<dim3(32, 4), 256>>>(core[2]);
    foldG45_kernel<<<64, 256>>>(core[4], core[5]);   // <-- FIX: was (core[3], core[4])
    foldB_kernel<<<128, 256>>>(core[3]);
    gemm1_kernel<<<128, 256, g1_smem>>>(x);
    gemm2_kernel<<<dim3(64, 32), 256, g2_smem>>>(bias, y);
}

// round 6
// speedup vs baseline: 2.2080x; 1.3231x over previous
#include <cuda_runtime.h>
#include <cstdint>

// ===========================================================================
// TT-linear via rank-64 bottleneck:  W = A(4096x64) @ B(64x4096)
//   t = x @ B^T      (mma.sync tf32, split-K=2, cp.async 4-stage ring)
//   y = t @ A^T + b  (mma.sync tf32, K=64 one-shot, 128x256 tiles)
// ===========================================================================
__device__ __align__(256) float g_A[4096 * 64];     // A (out, r)  tf32-rounded
__device__ __align__(256) float g_G45[64 * 256];    // fold(core4,core5)
__device__ __align__(256) float g_B[64 * 4096];     // B (r, in)   tf32-rounded
__device__ __align__(256) float g_T[2][8192 * 64];  // split-K partials of t

// ---------------- helpers ---------------------------------------------------
__device__ __forceinline__ uint32_t smem_u32(const void* p) {
    uint32_t a;
    asm("{ .reg .u64 t; cvta.to.shared.u64 t, %1; cvt.u32.u64 %0, t; }" : "=r"(a) : "l"(p));
    return a;
}
__device__ __forceinline__ float rna(float v) {
    uint32_t r; asm("cvt.rna.tf32.f32 %0, %1;" : "=r"(r) : "f"(v));
    return __uint_as_float(r);
}
__device__ __forceinline__ void cp16(uint32_t dst, const void* src) {
    asm volatile("cp.async.cg.shared.global [%0], [%1], 16;" :: "r"(dst), "l"(src));
}
#define CP_COMMIT() asm volatile("cp.async.commit_group;" ::: "memory")
#define CP_WAIT2()  asm volatile("cp.async.wait_group 2;" ::: "memory")

// D += A * B   (m16n8k8, tf32 inputs in b32 regs, f32 accum)
__device__ __forceinline__ void mma8(float* c, const uint32_t* a, const uint32_t* b) {
    asm volatile(
        "mma.sync.aligned.m16n8k8.row.col.f32.tf32.tf32.f32 "
        "{%0,%1,%2,%3}, {%4,%5,%6,%7}, {%8,%9}, {%0,%1,%2,%3};"
        : "+f"(c[0]), "+f"(c[1]), "+f"(c[2]), "+f"(c[3])
        : "r"(a[0]), "r"(a[1]), "r"(a[2]), "r"(a[3]), "r"(b[0]), "r"(b[1]));
}

// ---------------------------------------------------------------------------
// Folds. Core shapes: G0(1,16,64) G1..G4(64,16,64) G5(64,16,1).
// ---------------------------------------------------------------------------
// A path fused: block b of 1024 -> row r=b>>2 of flat (256,1024) A, cols (b&3)*256+tid.
// Each block recomputes its w01 row (64 elems, 64 MAC each) in smem.
__global__ __launch_bounds__(256) void fold12_kernel(const float* __restrict__ G0,
                                                     const float* __restrict__ G1,
                                                     const float* __restrict__ G2) {
    __shared__ float w01row[64];
    const int b = blockIdx.x;
    const int r = b >> 2, s0 = r >> 4, s1 = r & 15;
    const int tid = threadIdx.x;
    if (tid < 64) {
        float s = 0.f;
#pragma unroll
        for (int r1 = 0; r1 < 64; ++r1)
            s += G0[s0 * 64 + r1] * G1[r1 * 1024 + s1 * 64 + tid];
        w01row[tid] = s;
    }
    __syncthreads();
    const int c = (b & 3) * 256 + tid;
    float a0 = 0.f, a1 = 0.f, a2 = 0.f, a3 = 0.f;
#pragma unroll
    for (int r2 = 0; r2 < 64; r2 += 4) {
        a0 += w01row[r2]     * G2[r2 * 1024 + c];
        a1 += w01row[r2 + 1] * G2[(r2 + 1) * 1024 + c];
        a2 += w01row[r2 + 2] * G2[(r2 + 2) * 1024 + c];
        a3 += w01row[r2 + 3] * G2[(r2 + 3) * 1024 + c];
    }
    g_A[(size_t)r * 1024 + c] = rna((a0 + a1) + (a2 + a3));
}

__global__ void foldG45_kernel(const float* __restrict__ G4, const float* __restrict__ G5) {
    int i = blockIdx.x * 256 + threadIdx.x;       // 16384: G45[r4][(s4,s5)]
    int r4 = i >> 8, s4 = (i >> 4) & 15, s5 = i & 15;
    float s = 0.f;
#pragma unroll
    for (int r5 = 0; r5 < 64; ++r5) s += G4[r4 * 1024 + s4 * 64 + r5] * G5[r5 * 16 + s5];
    g_G45[i] = s;
}

// B[(r3,s3)][(s4,s5)]: flat (1024,256) == (64,4096) row-major. 1024 blocks, 1 out/thread.
__global__ __launch_bounds__(256) void foldB_kernel(const float* __restrict__ G3) {
    const int b = blockIdx.x;       // output row 0..1023
    const int c = threadIdx.x;      // output col 0..255
    float a0 = 0.f, a1 = 0.f, a2 = 0.f, a3 = 0.f;
#pragma unroll
    for (int r4 = 0; r4 < 64; r4 += 4) {
        a0 += G3[b * 64 + r4]     * g_G45[r4 * 256 + c];
        a1 += G3[b * 64 + r4 + 1] * g_G45[(r4 + 1) * 256 + c];
        a2 += G3[b * 64 + r4 + 2] * g_G45[(r4 + 2) * 256 + c];
        a3 += G3[b * 64 + r4 + 3] * g_G45[(r4 + 3) * 256 + c];
    }
    g_B[(size_t)b * 256 + c] = rna((a0 + a1) + (a2 + a3));
}

// ---------------------------------------------------------------------------
// GEMM1: t[n,r] = sum_k x[n,k]*B[r,k].  M=8192 N=64 K=4096, split-K=2.
// grid (64,2) = 128 CTAs. CTA tile 128 tok x 64 r, 256 threads, 8 warps 4x2,
// warp tile 32x32. K chunks of 32, 4-stage cp.async ring.
// Stage layout: x 128 rows x 144B (18432B) then B 64 x 144B (9216B); stride 27648.
// ---------------------------------------------------------------------------
__global__ __launch_bounds__(256) void gemm1_kernel(const float* __restrict__ x) {
    extern __shared__ char sm[];
    const uint32_t sb = smem_u32(sm);
    const int tid = threadIdx.x;
    const int warp = tid >> 5, lane = tid & 31;
    const int wm = warp >> 1, wn = warp & 1;      // warp origin (wm*32, wn*32)
    const int tok0 = blockIdx.x * 128;
    const int kbase = blockIdx.y * 2048;
    const int qr = (tid & 7) * 4;                 // float col within 32-chunk
    const int row0 = tid >> 3;                    // 0..31

    float acc[2][4][4];
#pragma unroll
    for (int a = 0; a < 2; ++a)
#pragma unroll
        for (int b = 0; b < 4; ++b)
#pragma unroll
            for (int c = 0; c < 4; ++c) acc[a][b][c] = 0.f;

    auto issue = [&](int chunk, int s) {
        int kc = kbase + chunk * 32;
        uint32_t xd = sb + s * 27648;
        uint32_t bd = xd + 18432;
#pragma unroll
        for (int l = 0; l < 4; ++l) {
            int r = row0 + 32 * l;
            cp16(xd + (uint32_t)(r * 144 + qr * 4), &x[(size_t)(tok0 + r) * 4096 + kc + qr]);
        }
#pragma unroll
        for (int l = 0; l < 2; ++l) {
            int r = row0 + 32 * l;
            cp16(bd + (uint32_t)(r * 144 + qr * 4), &g_B[(size_t)r * 4096 + kc + qr]);
        }
    };

    issue(0, 0); CP_COMMIT();
    issue(1, 1); CP_COMMIT();
    issue(2, 2); CP_COMMIT();

    const int lr = lane >> 2, lc = lane & 3;
    for (int i = 0; i < 64; ++i) {
        CP_WAIT2();
        __syncthreads();
        if (i + 3 < 64) issue(i + 3, (i + 3) & 3);
        CP_COMMIT();    // empty group at tail keeps wait_group 2 uniform

        const float* xs = reinterpret_cast<const float*>(sm + (i & 3) * 27648);
        const float* bs = reinterpret_cast<const float*>(sm + (i & 3) * 27648 + 18432);
#pragma unroll
        for (int k8 = 0; k8 < 4; ++k8) {
            const int kk = k8 * 8 + lc;
            uint32_t af[2][4], bf[4][2];
#pragma unroll
            for (int mt = 0; mt < 2; ++mt) {
                int r = wm * 32 + mt * 16 + lr;
                af[mt][0] = __float_as_uint(xs[r * 36 + kk]);
                af[mt][1] = __float_as_uint(xs[(r + 8) * 36 + kk]);
                af[mt][2] = __float_as_uint(xs[r * 36 + kk + 4]);
                af[mt][3] = __float_as_uint(xs[(r + 8) * 36 + kk + 4]);
            }
#pragma unroll
            for (int nt = 0; nt < 4; ++nt) {
                int n = wn * 32 + nt * 8 + lr;
                bf[nt][0] = __float_as_uint(bs[n * 36 + kk]);
                bf[nt][1] = __float_as_uint(bs[n * 36 + kk + 4]);
            }
#pragma unroll
            for (int mt = 0; mt < 2; ++mt)
#pragma unroll
                for (int nt = 0; nt < 4; ++nt) mma8(acc[mt][nt], af[mt], bf[nt]);
        }
    }

    // epilogue: raw fp32 partials (rounded in gemm2 after the add)
    float* tp = g_T[blockIdx.y];
#pragma unroll
    for (int mt = 0; mt < 2; ++mt)
#pragma unroll
        for (int nt = 0; nt < 4; ++nt)
#pragma unroll
            for (int h = 0; h < 2; ++h) {
                int r = tok0 + wm * 32 + mt * 16 + lr + 8 * h;
                int c = wn * 32 + nt * 8 + 2 * lc;
                *reinterpret_cast<float2*>(&tp[(size_t)r * 64 + c]) =
                    make_float2(acc[mt][nt][2 * h], acc[mt][nt][2 * h + 1]);
            }
}

// ---------------------------------------------------------------------------
// GEMM2: y[n,o] = sum_r t[n,r]*A[o,r] + b[o].  M=8192 N=4096 K=64.
// grid (64,16) = 1024 CTAs. CTA tile 128 tok x 256 out, 256 threads,
// 8 warps 2x4, warp tile 64x64. K=64 one-shot (rows padded to 68 floats).
// ---------------------------------------------------------------------------
__global__ __launch_bounds__(256) void gemm2_kernel(const float* __restrict__ bias,
                                                    float* __restrict__ y) {
    extern __shared__ char sm[];
    float* st = reinterpret_cast<float*>(sm);                 // [128][68]
    float* sa = reinterpret_cast<float*>(sm) + 128 * 68;      // [256][68]
    const int tid = threadIdx.x;
    const int warp = tid >> 5, lane = tid & 31;
    const int wm = warp >> 2, wn = warp & 3;      // warp origin (wm*64, wn*64)
    const int tok0 = blockIdx.x * 128, out0 = blockIdx.y * 256;

    // t tile: reduce split-K partials, round to tf32.  128x64 = 2048 f4 slots.
#pragma unroll
    for (int l = 0; l < 8; ++l) {
        int s = tid + 256 * l, row = s >> 4, q = (s & 15) * 4;
        float4 v0 = *reinterpret_cast<const float4*>(&g_T[0][(size_t)(tok0 + row) * 64 + q]);
        float4 v1 = *reinterpret_cast<const float4*>(&g_T[1][(size_t)(tok0 + row) * 64 + q]);
        st[row * 68 + q + 0] = rna(v0.x + v1.x);
        st[row * 68 + q + 1] = rna(v0.y + v1.y);
        st[row * 68 + q + 2] = rna(v0.z + v1.z);
        st[row * 68 + q + 3] = rna(v0.w + v1.w);
    }
    // A tile: 256x64 = 4096 f4 slots.
#pragma unroll
    for (int l = 0; l < 16; ++l) {
        int s = tid + 256 * l, row = s >> 4, q = (s & 15) * 4;
        *reinterpret_cast<float4*>(&sa[row * 68 + q]) =
            *reinterpret_cast<const float4*>(&g_A[(size_t)(out0 + row) * 64 + q]);
    }
    __syncthreads();

    float acc[4][8][4];
#pragma unroll
    for (int a = 0; a < 4; ++a)
#pragma unroll
        for (int b = 0; b < 8; ++b)
#pragma unroll
            for (int c = 0; c < 4; ++c) acc[a][b][c] = 0.f;

    const int lr = lane >> 2, lc = lane & 3;
#pragma unroll
    for (int k8 = 0; k8 < 8; ++k8) {
        const int kk = k8 * 8 + lc;
        uint32_t af[4][4], bf[8][2];
#pragma unroll
        for (int mt = 0; mt < 4; ++mt) {
            int r = wm * 64 + mt * 16 + lr;
            af[mt][0] = __float_as_uint(st[r * 68 + kk]);
            af[mt][1] = __float_as_uint(st[(r + 8) * 68 + kk]);
            af[mt][2] = __float_as_uint(st[r * 68 + kk + 4]);
            af[mt][3] = __float_as_uint(st[(r + 8) * 68 + kk + 4]);
        }
#pragma unroll
        for (int nt = 0; nt < 8; ++nt) {
            int n = wn * 64 + nt * 8 + lr;
            bf[nt][0] = __float_as_uint(sa[n * 68 + kk]);
            bf[nt][1] = __float_as_uint(sa[n * 68 + kk + 4]);
        }
#pragma unroll
        for (int mt = 0; mt < 4; ++mt)
#pragma unroll
            for (int nt = 0; nt < 8; ++nt) mma8(acc[mt][nt], af[mt], bf[nt]);
    }

    float2 bv[8];
#pragma unroll
    for (int nt = 0; nt < 8; ++nt)
        bv[nt] = *reinterpret_cast<const float2*>(&bias[out0 + wn * 64 + nt * 8 + 2 * lc]);

#pragma unroll
    for (int mt = 0; mt < 4; ++mt)
#pragma unroll
        for (int h = 0; h < 2; ++h) {
            int r = tok0 + wm * 64 + mt * 16 + lr + 8 * h;
            float* yr = y + (size_t)r * 4096 + out0 + wn * 64;
#pragma unroll
            for (int nt = 0; nt < 8; ++nt) {
                *reinterpret_cast<float2*>(&yr[nt * 8 + 2 * lc]) =
                    make_float2(acc[mt][nt][2 * h] + bv[nt].x,
                                acc[mt][nt][2 * h + 1] + bv[nt].y);
            }
        }
}

// ---------------------------------------------------------------------------
// Launch
// ---------------------------------------------------------------------------
extern "C" void kernel_launch(void* const* d_in, const int* in_sizes, int n_in,
                              void* d_out, int out_size) {
    const float* core[6] = {nullptr, nullptr, nullptr, nullptr, nullptr, nullptr};
    const float* x = nullptr;
    const float* bias = nullptr;
    int c64 = 1;
    for (int i = 0; i < n_in; ++i) {
        int sz = in_sizes[i];
        const float* p = reinterpret_cast<const float*>(d_in[i]);
        if (sz == 8192 * 4096) x = p;
        else if (sz == 4096) bias = p;
        else if (sz == 65536) { if (c64 <= 4) core[c64++] = p; }
        else if (sz == 1024) { if (!core[0]) core[0] = p; else core[5] = p; }
    }
    float* y = reinterpret_cast<float*>(d_out);

    const int g1_smem = 4 * 27648;                  // 110592
    const int g2_smem = (128 + 256) * 68 * 4;       // 104448
    cudaFuncSetAttribute(gemm1_kernel, cudaFuncAttributeMaxDynamicSharedMemorySize, g1_smem);
    cudaFuncSetAttribute(gemm2_kernel, cudaFuncAttributeMaxDynamicSharedMemorySize, g2_smem);

    foldG45_kernel<<<64, 256>>>(core[4], core[5]);
    foldB_kernel<<<1024, 256>>>(core[3]);
    fold12_kernel<<<1024, 256>>>(core[0], core[1], core[2]);
    gemm1_kernel<<<dim3(64, 2), 256, g1_smem>>>(x);
    gemm2_kernel<<<dim3(64, 16), 256, g2_smem>>>(bias, y);
}